// round 7
// baseline (speedup 1.0000x reference)
#include <cuda_runtime.h>

// Problem constants (fixed by the reference)
#define NN 50000          // nodes
#define NE 800000         // edges
#define DD 96             // feature dim
#define D4 24             // DD / 4 (float4 groups)

// ---------------- scratch (device globals; no allocation allowed) ----------
__device__ float g_x[NN * DD];   // norm_src-scaled features
__device__ float g_m[NN * DD];   // scatter-add accumulator
__device__ float g_h[NN * DD];   // layer output ping buffer
__device__ int   g_od[NN];       // out degree (src side)
__device__ int   g_id[NN];       // in degree (dst side)
__device__ float g_ns[NN];       // out_deg^-1/2
__device__ float g_nd[NN];       // in_deg^-1/2
__device__ int   g_is64;         // 1 if index arrays are int64, 0 if int32

// ---------------- index dtype probe ----------------------------------------
// If the buffers hold int32 node ids, reading them as int64 packs two ids per
// word -> value >= 2^32 unless the high id happens to be 0 (prob 1/50000 per
// sample; 256 samples -> detection is certain in practice).
__global__ void k_detect(const void* src, const void* dst) {
    __shared__ int bad;
    if (threadIdx.x == 0) bad = 0;
    __syncthreads();
    const long long* s = (const long long*)src;
    const long long* d = (const long long*)dst;
    long long v1 = s[threadIdx.x];
    long long v2 = d[threadIdx.x];
    if (v1 < 0 || v1 >= NN || v2 < 0 || v2 >= NN) bad = 1;
    __syncthreads();
    if (threadIdx.x == 0) g_is64 = bad ? 0 : 1;
}

__device__ __forceinline__ int load_idx(const void* p, int e, int is64) {
    if (is64) return (int)((const long long*)p)[e];
    return ((const int*)p)[e];
}

// ---------------- degrees / norms -------------------------------------------
__global__ void k_zero_deg() {
    int i = blockIdx.x * blockDim.x + threadIdx.x;
    if (i < NN) { g_od[i] = 0; g_id[i] = 0; }
}

__global__ void k_deg(const void* __restrict__ src, const void* __restrict__ dst) {
    int e = blockIdx.x * blockDim.x + threadIdx.x;
    if (e < NE) {
        int is64 = g_is64;
        atomicAdd(&g_od[load_idx(src, e, is64)], 1);
        atomicAdd(&g_id[load_idx(dst, e, is64)], 1);
    }
}

__global__ void k_norm() {
    int i = blockIdx.x * blockDim.x + threadIdx.x;
    if (i < NN) {
        g_ns[i] = rsqrtf((float)max(g_od[i], 1));
        g_nd[i] = rsqrtf((float)max(g_id[i], 1));
    }
}

// ---------------- per-layer: scale h by norm_src, zero m --------------------
__global__ void k_scale_zero(const float* __restrict__ hin, int use_g) {
    int idx = blockIdx.x * blockDim.x + threadIdx.x;
    if (idx < NN * D4) {
        int node = idx / D4;
        const float4* h4 = use_g ? (const float4*)g_h : (const float4*)hin;
        float4 v = h4[idx];
        float s = g_ns[node];
        v.x *= s; v.y *= s; v.z *= s; v.w *= s;
        ((float4*)g_x)[idx] = v;
        ((float4*)g_m)[idx] = make_float4(0.f, 0.f, 0.f, 0.f);
    }
}

// ---------------- edge scatter-add ------------------------------------------
// 24 threads per edge; each thread moves one float4. x and m both L2-resident.
__global__ void k_scatter(const void* __restrict__ src, const void* __restrict__ dst) {
    int idx = blockIdx.x * blockDim.x + threadIdx.x;
    if (idx < NE * D4) {
        int e = idx / D4;
        int g = idx - e * D4;
        int is64 = g_is64;
        int s = load_idx(src, e, is64);
        int d = load_idx(dst, e, is64);
        float4 v = ((const float4*)g_x)[s * D4 + g];
        float* mp = &g_m[d * DD + g * 4];
        atomicAdd(mp + 0, v.x);
        atomicAdd(mp + 1, v.y);
        atomicAdd(mp + 2, v.z);
        atomicAdd(mp + 3, v.w);
    }
}

// ---------------- GEMM + norm_dst + bias + relu ------------------------------
// out[i][j] = relu(b[j] + norm_dst[i] * sum_k m[i][k] * W[k][j])
// Block: 192 threads, 32-row tile. W (36KB) + M-tile (12KB) fully in smem.
// Threads: ct = tid%24 -> 4 cols, rt = tid/24 -> 4 rows. 4x4 register tile.
__global__ __launch_bounds__(192) void k_gemm(const float* __restrict__ W,
                                              const float* __restrict__ B,
                                              float* __restrict__ out /* null -> g_h */) {
    __shared__ float Ws[DD * DD];   // 36864 B
    __shared__ float Ms[32 * DD];   // 12288 B  (total 49152 = 48KB)
    int tid = threadIdx.x;
    int row0 = blockIdx.x * 32;

    // Load W: 2304 float4 / 192 threads = 12 each
    const float4* W4 = (const float4*)W;
    float4* Ws4 = (float4*)Ws;
#pragma unroll
    for (int i = 0; i < 12; i++) Ws4[tid + i * 192] = W4[tid + i * 192];

    // Load M tile: 768 float4 / 192 threads = 4 each (zero-fill OOB rows)
#pragma unroll
    for (int i = 0; i < 4; i++) {
        int li = tid + i * 192;          // 0..767
        int r = li / D4;
        int c4 = li - r * D4;
        int row = row0 + r;
        float4 v = make_float4(0.f, 0.f, 0.f, 0.f);
        if (row < NN) v = ((const float4*)g_m)[row * D4 + c4];
        ((float4*)Ms)[li] = v;
    }
    __syncthreads();

    int ct = tid % 24;    // column group (4 cols)
    int rt = tid / 24;    // row group (4 rows)

    float acc[4][4];
#pragma unroll
    for (int rr = 0; rr < 4; rr++)
#pragma unroll
        for (int cc = 0; cc < 4; cc++) acc[rr][cc] = 0.f;

#pragma unroll
    for (int k = 0; k < DD; k += 4) {
        float wreg[4][4];
#pragma unroll
        for (int kk = 0; kk < 4; kk++)
            *(float4*)(&wreg[kk][0]) = *(const float4*)(Ws + (k + kk) * DD + ct * 4);
#pragma unroll
        for (int rr = 0; rr < 4; rr++) {
            float mreg[4];
            *(float4*)mreg = *(const float4*)(Ms + (rt * 4 + rr) * DD + k);
#pragma unroll
            for (int kk = 0; kk < 4; kk++)
#pragma unroll
                for (int cc = 0; cc < 4; cc++)
                    acc[rr][cc] = fmaf(mreg[kk], wreg[kk][cc], acc[rr][cc]);
        }
    }

    float bb[4];
    *(float4*)bb = *(const float4*)(B + ct * 4);
    float* op = out ? out : g_h;
#pragma unroll
    for (int rr = 0; rr < 4; rr++) {
        int row = row0 + rt * 4 + rr;
        if (row < NN) {
            float nd = g_nd[row];
            float oo[4];
#pragma unroll
            for (int cc = 0; cc < 4; cc++)
                oo[cc] = fmaxf(fmaf(nd, acc[rr][cc], bb[cc]), 0.f);
            *(float4*)(op + row * DD + ct * 4) = *(float4*)oo;
        }
    }
}

// ---------------- launch ------------------------------------------------------
extern "C" void kernel_launch(void* const* d_in, const int* in_sizes, int n_in,
                              void* d_out, int out_size) {
    const float* h   = (const float*)d_in[0];
    const void*  src = d_in[1];
    const void*  dst = d_in[2];
    const float* Wl[3] = { (const float*)d_in[3], (const float*)d_in[5], (const float*)d_in[7] };
    const float* Bl[3] = { (const float*)d_in[4], (const float*)d_in[6], (const float*)d_in[8] };

    k_detect<<<1, 256>>>(src, dst);
    k_zero_deg<<<(NN + 255) / 256, 256>>>();
    k_deg<<<(NE + 255) / 256, 256>>>(src, dst);
    k_norm<<<(NN + 255) / 256, 256>>>();

    for (int l = 0; l < 3; l++) {
        k_scale_zero<<<(NN * D4 + 255) / 256, 256>>>(h, l > 0 ? 1 : 0);
        k_scatter<<<(NE * D4 + 255) / 256, 256>>>(src, dst);
        k_gemm<<<(NN + 31) / 32, 192>>>(Wl[l], Bl[l], l == 2 ? (float*)d_out : nullptr);
    }
}

// round 8
// speedup vs baseline: 2.2290x; 2.2290x over previous
#include <cuda_runtime.h>

// Problem constants (fixed by the reference)
#define NN 50000          // nodes
#define NE 800000         // edges
#define DD 96             // feature dim
#define D4 24             // DD / 4 (float4 groups)

// ---------------- scratch (device globals; no allocation allowed) ----------
__device__ float g_x[NN * DD];     // norm_src-scaled features (layer input)
__device__ float g_m[NN * DD];     // aggregated messages (already * norm_dst)
__device__ int   g_od[NN];         // out degree (src side)
__device__ int   g_id[NN];         // in degree (dst side)
__device__ float g_ns[NN];         // out_deg^-1/2
__device__ float g_nd[NN];         // in_deg^-1/2
__device__ int   g_off[NN + 1];    // CSR offsets (by dst)
__device__ int   g_cur[NN];        // CSR fill cursors
__device__ int   g_eidx[NE];       // src ids grouped by dst
__device__ int   g_is64;           // 1 if index arrays are int64, 0 if int32

// ---------------- index dtype probe ----------------------------------------
// If the buffers hold int32 ids, reading as int64 packs two ids per word ->
// value >= 2^32 unless the high id is 0 (prob 1/50000 per sample; 256 samples
// -> detection certain in practice).
__global__ void k_detect(const void* src, const void* dst) {
    __shared__ int bad;
    if (threadIdx.x == 0) bad = 0;
    __syncthreads();
    const long long* s = (const long long*)src;
    const long long* d = (const long long*)dst;
    long long v1 = s[threadIdx.x];
    long long v2 = d[threadIdx.x];
    if (v1 < 0 || v1 >= NN || v2 < 0 || v2 >= NN) bad = 1;
    __syncthreads();
    if (threadIdx.x == 0) g_is64 = bad ? 0 : 1;
}

__device__ __forceinline__ int load_idx(const void* p, int e, int is64) {
    if (is64) return (int)((const long long*)p)[e];
    return ((const int*)p)[e];
}

// ---------------- degrees / norms -------------------------------------------
__global__ void k_zero_deg() {
    int i = blockIdx.x * blockDim.x + threadIdx.x;
    if (i < NN) { g_od[i] = 0; g_id[i] = 0; }
}

__global__ void k_deg(const void* __restrict__ src, const void* __restrict__ dst) {
    int e = blockIdx.x * blockDim.x + threadIdx.x;
    if (e < NE) {
        int is64 = g_is64;
        atomicAdd(&g_od[load_idx(src, e, is64)], 1);
        atomicAdd(&g_id[load_idx(dst, e, is64)], 1);
    }
}

__global__ void k_norm() {
    int i = blockIdx.x * blockDim.x + threadIdx.x;
    if (i < NN) {
        g_ns[i] = rsqrtf((float)max(g_od[i], 1));
        g_nd[i] = rsqrtf((float)max(g_id[i], 1));
    }
}

// ---------------- CSR build: exclusive scan of in-degrees -------------------
// Single block, 1024 threads, 49 consecutive nodes per thread (two passes).
#define SCAN_T 1024
#define CHUNK 49   // 1024*49 = 50176 >= NN
__global__ void k_scan() {
    int t = threadIdx.x;
    int s0 = t * CHUNK;
    int sum = 0;
    for (int i = 0; i < CHUNK; i++) {
        int n = s0 + i;
        if (n < NN) sum += g_id[n];
    }
    // block exclusive scan of per-thread sums
    __shared__ int wsum[32];
    int lane = t & 31, wid = t >> 5;
    int v = sum;
    for (int o = 1; o < 32; o <<= 1) {
        int u = __shfl_up_sync(0xffffffffu, v, o);
        if (lane >= o) v += u;
    }
    if (lane == 31) wsum[wid] = v;
    __syncthreads();
    if (wid == 0) {
        int w = wsum[lane];
        for (int o = 1; o < 32; o <<= 1) {
            int u = __shfl_up_sync(0xffffffffu, w, o);
            if (lane >= o) w += u;
        }
        wsum[lane] = w;
    }
    __syncthreads();
    int run = v - sum + (wid > 0 ? wsum[wid - 1] : 0);  // exclusive prefix
    for (int i = 0; i < CHUNK; i++) {
        int n = s0 + i;
        if (n < NN) {
            g_off[n] = run;
            g_cur[n] = run;
            run += g_id[n];
        }
    }
    if (t == SCAN_T - 1) g_off[NN] = run;  // == NE
}

__global__ void k_fill(const void* __restrict__ src, const void* __restrict__ dst) {
    int e = blockIdx.x * blockDim.x + threadIdx.x;
    if (e < NE) {
        int is64 = g_is64;
        int s = load_idx(src, e, is64);
        int d = load_idx(dst, e, is64);
        int pos = atomicAdd(&g_cur[d], 1);
        g_eidx[pos] = s;
    }
}

// ---------------- layer 0 input: x = h * norm_src ---------------------------
__global__ void k_scale_x(const float* __restrict__ hin) {
    int idx = blockIdx.x * blockDim.x + threadIdx.x;
    if (idx < NN * D4) {
        int node = idx / D4;
        float4 v = ((const float4*)hin)[idx];
        float s = g_ns[node];
        v.x *= s; v.y *= s; v.z *= s; v.w *= s;
        ((float4*)g_x)[idx] = v;
    }
}

// ---------------- CSR gather: m[d] = nd[d] * sum_{e in CSR[d]} x[src[e]] -----
// One warp per dst node. Lanes batch-load 32 edge indices (coalesced), then
// shuffle-broadcast each src; each lane accumulates 3 features (lane, +32, +64).
// Pure reads (x is L2-resident), no float atomics, no zeroing of m needed.
__global__ __launch_bounds__(256) void k_gather() {
    int warp = (blockIdx.x * blockDim.x + threadIdx.x) >> 5;
    int lane = threadIdx.x & 31;
    if (warp >= NN) return;
    int beg = g_off[warp];
    int end = g_off[warp + 1];
    float a0 = 0.f, a1 = 0.f, a2 = 0.f;
    for (int base = beg; base < end; base += 32) {
        int n = min(32, end - base);
        int idx = (base + lane < end) ? g_eidx[base + lane] : 0;
        for (int j = 0; j < n; j++) {
            int s = __shfl_sync(0xffffffffu, idx, j);
            const float* xp = g_x + s * DD;
            a0 += xp[lane];
            a1 += xp[lane + 32];
            a2 += xp[lane + 64];
        }
    }
    float nd = g_nd[warp];
    float* mp = g_m + warp * DD;
    mp[lane]      = a0 * nd;
    mp[lane + 32] = a1 * nd;
    mp[lane + 64] = a2 * nd;
}

// ---------------- GEMM + bias + relu (+ fused norm_src for next layer) ------
// out[i][j] = relu(b[j] + sum_k m[i][k] * W[k][j]); if writing g_x for the next
// layer, additionally multiply by norm_src[i].
// Block: 192 threads, 32-row tile. W (36KB) + M-tile (12KB) in smem (48KB).
__global__ __launch_bounds__(192) void k_gemm(const float* __restrict__ W,
                                              const float* __restrict__ B,
                                              float* __restrict__ out /* null -> g_x (scaled by ns) */) {
    __shared__ float Ws[DD * DD];   // 36864 B
    __shared__ float Ms[32 * DD];   // 12288 B
    int tid = threadIdx.x;
    int row0 = blockIdx.x * 32;

    const float4* W4 = (const float4*)W;
    float4* Ws4 = (float4*)Ws;
#pragma unroll
    for (int i = 0; i < 12; i++) Ws4[tid + i * 192] = W4[tid + i * 192];

#pragma unroll
    for (int i = 0; i < 4; i++) {
        int li = tid + i * 192;          // 0..767
        int r = li / D4;
        int c4 = li - r * D4;
        int row = row0 + r;
        float4 v = make_float4(0.f, 0.f, 0.f, 0.f);
        if (row < NN) v = ((const float4*)g_m)[row * D4 + c4];
        ((float4*)Ms)[li] = v;
    }
    __syncthreads();

    int ct = tid % 24;    // column group (4 cols)
    int rt = tid / 24;    // row group (4 rows)

    float acc[4][4];
#pragma unroll
    for (int rr = 0; rr < 4; rr++)
#pragma unroll
        for (int cc = 0; cc < 4; cc++) acc[rr][cc] = 0.f;

#pragma unroll
    for (int k = 0; k < DD; k += 4) {
        float wreg[4][4];
#pragma unroll
        for (int kk = 0; kk < 4; kk++)
            *(float4*)(&wreg[kk][0]) = *(const float4*)(Ws + (k + kk) * DD + ct * 4);
#pragma unroll
        for (int rr = 0; rr < 4; rr++) {
            float mreg[4];
            *(float4*)mreg = *(const float4*)(Ms + (rt * 4 + rr) * DD + k);
#pragma unroll
            for (int kk = 0; kk < 4; kk++)
#pragma unroll
                for (int cc = 0; cc < 4; cc++)
                    acc[rr][cc] = fmaf(mreg[kk], wreg[kk][cc], acc[rr][cc]);
        }
    }

    float bb[4];
    *(float4*)bb = *(const float4*)(B + ct * 4);
#pragma unroll
    for (int rr = 0; rr < 4; rr++) {
        int row = row0 + rt * 4 + rr;
        if (row < NN) {
            float oo[4];
#pragma unroll
            for (int cc = 0; cc < 4; cc++)
                oo[cc] = fmaxf(acc[rr][cc] + bb[cc], 0.f);
            if (out) {
                *(float4*)(out + row * DD + ct * 4) = *(float4*)oo;
            } else {
                float ns = g_ns[row];   // pre-scale for the next layer's gather
#pragma unroll
                for (int cc = 0; cc < 4; cc++) oo[cc] *= ns;
                *(float4*)(g_x + row * DD + ct * 4) = *(float4*)oo;
            }
        }
    }
}

// ---------------- launch ------------------------------------------------------
extern "C" void kernel_launch(void* const* d_in, const int* in_sizes, int n_in,
                              void* d_out, int out_size) {
    const float* h   = (const float*)d_in[0];
    const void*  src = d_in[1];
    const void*  dst = d_in[2];
    const float* Wl[3] = { (const float*)d_in[3], (const float*)d_in[5], (const float*)d_in[7] };
    const float* Bl[3] = { (const float*)d_in[4], (const float*)d_in[6], (const float*)d_in[8] };

    k_detect<<<1, 256>>>(src, dst);
    k_zero_deg<<<(NN + 255) / 256, 256>>>();
    k_deg<<<(NE + 255) / 256, 256>>>(src, dst);
    k_norm<<<(NN + 255) / 256, 256>>>();
    k_scan<<<1, SCAN_T>>>();
    k_fill<<<(NE + 255) / 256, 256>>>(src, dst);

    k_scale_x<<<(NN * D4 + 255) / 256, 256>>>(h);
    for (int l = 0; l < 3; l++) {
        k_gather<<<(NN * 32 + 255) / 256, 256>>>();
        k_gemm<<<(NN + 31) / 32, 192>>>(Wl[l], Bl[l], l == 2 ? (float*)d_out : nullptr);
    }
}

// round 9
// speedup vs baseline: 2.2382x; 1.0041x over previous
#include <cuda_runtime.h>

// Problem constants (fixed by the reference)
#define NN 50000          // nodes
#define NE 800000         // edges
#define DD 96             // feature dim
#define D4 24             // DD / 4 (float4 groups)

// ---------------- scratch (device globals; no allocation allowed) ----------
__device__ float g_x[NN * DD];     // norm_src-scaled features (layer input)
__device__ float g_m[NN * DD];     // aggregated messages (already * norm_dst)
__device__ int   g_od[NN];         // out degree (src side)
__device__ int   g_id[NN];         // in degree (dst side)
__device__ float g_ns[NN];         // out_deg^-1/2
__device__ float g_nd[NN];         // in_deg^-1/2
__device__ int   g_off[NN + 1];    // CSR offsets (by dst)
__device__ int   g_cur[NN];        // CSR fill cursors
__device__ int   g_eidx[NE];       // src ids grouped by dst
__device__ int   g_is64;           // 1 if index arrays are int64, 0 if int32

// ---------------- index dtype probe ----------------------------------------
// If the buffers hold int32 ids, reading as int64 packs two ids per word ->
// value >= 2^32 unless the high id is 0 (prob 1/50000 per sample; 256 samples
// -> detection certain in practice).
__global__ void k_detect(const void* src, const void* dst) {
    __shared__ int bad;
    if (threadIdx.x == 0) bad = 0;
    __syncthreads();
    const long long* s = (const long long*)src;
    const long long* d = (const long long*)dst;
    long long v1 = s[threadIdx.x];
    long long v2 = d[threadIdx.x];
    if (v1 < 0 || v1 >= NN || v2 < 0 || v2 >= NN) bad = 1;
    __syncthreads();
    if (threadIdx.x == 0) g_is64 = bad ? 0 : 1;
}

__device__ __forceinline__ int load_idx(const void* p, int e, int is64) {
    if (is64) return (int)((const long long*)p)[e];
    return ((const int*)p)[e];
}

// ---------------- degrees / norms -------------------------------------------
__global__ void k_zero_deg() {
    int i = blockIdx.x * blockDim.x + threadIdx.x;
    if (i < NN) { g_od[i] = 0; g_id[i] = 0; }
}

__global__ void k_deg(const void* __restrict__ src, const void* __restrict__ dst) {
    int e = blockIdx.x * blockDim.x + threadIdx.x;
    if (e < NE) {
        int is64 = g_is64;
        atomicAdd(&g_od[load_idx(src, e, is64)], 1);
        atomicAdd(&g_id[load_idx(dst, e, is64)], 1);
    }
}

__global__ void k_norm() {
    int i = blockIdx.x * blockDim.x + threadIdx.x;
    if (i < NN) {
        g_ns[i] = rsqrtf((float)max(g_od[i], 1));
        g_nd[i] = rsqrtf((float)max(g_id[i], 1));
    }
}

// ---------------- CSR build: exclusive scan of in-degrees -------------------
// Single block, 1024 threads, 49 consecutive nodes per thread (two passes).
#define SCAN_T 1024
#define CHUNK 49   // 1024*49 = 50176 >= NN
__global__ void k_scan() {
    int t = threadIdx.x;
    int s0 = t * CHUNK;
    int sum = 0;
    for (int i = 0; i < CHUNK; i++) {
        int n = s0 + i;
        if (n < NN) sum += g_id[n];
    }
    // block exclusive scan of per-thread sums
    __shared__ int wsum[32];
    int lane = t & 31, wid = t >> 5;
    int v = sum;
    for (int o = 1; o < 32; o <<= 1) {
        int u = __shfl_up_sync(0xffffffffu, v, o);
        if (lane >= o) v += u;
    }
    if (lane == 31) wsum[wid] = v;
    __syncthreads();
    if (wid == 0) {
        int w = wsum[lane];
        for (int o = 1; o < 32; o <<= 1) {
            int u = __shfl_up_sync(0xffffffffu, w, o);
            if (lane >= o) w += u;
        }
        wsum[lane] = w;
    }
    __syncthreads();
    int run = v - sum + (wid > 0 ? wsum[wid - 1] : 0);  // exclusive prefix
    for (int i = 0; i < CHUNK; i++) {
        int n = s0 + i;
        if (n < NN) {
            g_off[n] = run;
            g_cur[n] = run;
            run += g_id[n];
        }
    }
    if (t == SCAN_T - 1) g_off[NN] = run;  // == NE
}

__global__ void k_fill(const void* __restrict__ src, const void* __restrict__ dst) {
    int e = blockIdx.x * blockDim.x + threadIdx.x;
    if (e < NE) {
        int is64 = g_is64;
        int s = load_idx(src, e, is64);
        int d = load_idx(dst, e, is64);
        int pos = atomicAdd(&g_cur[d], 1);
        g_eidx[pos] = s;
    }
}

// ---------------- layer 0 input: x = h * norm_src ---------------------------
__global__ void k_scale_x(const float* __restrict__ hin) {
    int idx = blockIdx.x * blockDim.x + threadIdx.x;
    if (idx < NN * D4) {
        int node = idx / D4;
        float4 v = ((const float4*)hin)[idx];
        float s = g_ns[node];
        v.x *= s; v.y *= s; v.z *= s; v.w *= s;
        ((float4*)g_x)[idx] = v;
    }
}

// ---------------- CSR gather: m[d] = nd[d] * sum_{e in CSR[d]} x[src[e]] -----
// One warp per dst node. Lanes batch-load 32 edge indices (coalesced), then
// shuffle-broadcast each src; each lane accumulates 3 features (lane, +32, +64).
// Pure reads (x is L2-resident), no float atomics, no zeroing of m needed.
__global__ __launch_bounds__(256) void k_gather() {
    int warp = (blockIdx.x * blockDim.x + threadIdx.x) >> 5;
    int lane = threadIdx.x & 31;
    if (warp >= NN) return;
    int beg = g_off[warp];
    int end = g_off[warp + 1];
    float a0 = 0.f, a1 = 0.f, a2 = 0.f;
    for (int base = beg; base < end; base += 32) {
        int n = min(32, end - base);
        int idx = (base + lane < end) ? g_eidx[base + lane] : 0;
        for (int j = 0; j < n; j++) {
            int s = __shfl_sync(0xffffffffu, idx, j);
            const float* xp = g_x + s * DD;
            a0 += xp[lane];
            a1 += xp[lane + 32];
            a2 += xp[lane + 64];
        }
    }
    float nd = g_nd[warp];
    float* mp = g_m + warp * DD;
    mp[lane]      = a0 * nd;
    mp[lane + 32] = a1 * nd;
    mp[lane + 64] = a2 * nd;
}

// ---------------- GEMM + bias + relu (+ fused norm_src for next layer) ------
// out[i][j] = relu(b[j] + sum_k m[i][k] * W[k][j]); if writing g_x for the next
// layer, additionally multiply by norm_src[i].
// Block: 192 threads, 32-row tile. W (36KB) + M-tile (12KB) in smem (48KB).
__global__ __launch_bounds__(192) void k_gemm(const float* __restrict__ W,
                                              const float* __restrict__ B,
                                              float* __restrict__ out /* null -> g_x (scaled by ns) */) {
    __shared__ float Ws[DD * DD];   // 36864 B
    __shared__ float Ms[32 * DD];   // 12288 B
    int tid = threadIdx.x;
    int row0 = blockIdx.x * 32;

    const float4* W4 = (const float4*)W;
    float4* Ws4 = (float4*)Ws;
#pragma unroll
    for (int i = 0; i < 12; i++) Ws4[tid + i * 192] = W4[tid + i * 192];

#pragma unroll
    for (int i = 0; i < 4; i++) {
        int li = tid + i * 192;          // 0..767
        int r = li / D4;
        int c4 = li - r * D4;
        int row = row0 + r;
        float4 v = make_float4(0.f, 0.f, 0.f, 0.f);
        if (row < NN) v = ((const float4*)g_m)[row * D4 + c4];
        ((float4*)Ms)[li] = v;
    }
    __syncthreads();

    int ct = tid % 24;    // column group (4 cols)
    int rt = tid / 24;    // row group (4 rows)

    float acc[4][4];
#pragma unroll
    for (int rr = 0; rr < 4; rr++)
#pragma unroll
        for (int cc = 0; cc < 4; cc++) acc[rr][cc] = 0.f;

#pragma unroll
    for (int k = 0; k < DD; k += 4) {
        float wreg[4][4];
#pragma unroll
        for (int kk = 0; kk < 4; kk++)
            *(float4*)(&wreg[kk][0]) = *(const float4*)(Ws + (k + kk) * DD + ct * 4);
#pragma unroll
        for (int rr = 0; rr < 4; rr++) {
            float mreg[4];
            *(float4*)mreg = *(const float4*)(Ms + (rt * 4 + rr) * DD + k);
#pragma unroll
            for (int kk = 0; kk < 4; kk++)
#pragma unroll
                for (int cc = 0; cc < 4; cc++)
                    acc[rr][cc] = fmaf(mreg[kk], wreg[kk][cc], acc[rr][cc]);
        }
    }

    float bb[4];
    *(float4*)bb = *(const float4*)(B + ct * 4);
#pragma unroll
    for (int rr = 0; rr < 4; rr++) {
        int row = row0 + rt * 4 + rr;
        if (row < NN) {
            float oo[4];
#pragma unroll
            for (int cc = 0; cc < 4; cc++)
                oo[cc] = fmaxf(acc[rr][cc] + bb[cc], 0.f);
            if (out) {
                *(float4*)(out + row * DD + ct * 4) = *(float4*)oo;
            } else {
                float ns = g_ns[row];   // pre-scale for the next layer's gather
#pragma unroll
                for (int cc = 0; cc < 4; cc++) oo[cc] *= ns;
                *(float4*)(g_x + row * DD + ct * 4) = *(float4*)oo;
            }
        }
    }
}

// ---------------- launch ------------------------------------------------------
extern "C" void kernel_launch(void* const* d_in, const int* in_sizes, int n_in,
                              void* d_out, int out_size) {
    const float* h   = (const float*)d_in[0];
    const void*  src = d_in[1];
    const void*  dst = d_in[2];
    const float* Wl[3] = { (const float*)d_in[3], (const float*)d_in[5], (const float*)d_in[7] };
    const float* Bl[3] = { (const float*)d_in[4], (const float*)d_in[6], (const float*)d_in[8] };

    k_detect<<<1, 256>>>(src, dst);
    k_zero_deg<<<(NN + 255) / 256, 256>>>();
    k_deg<<<(NE + 255) / 256, 256>>>(src, dst);
    k_norm<<<(NN + 255) / 256, 256>>>();
    k_scan<<<1, SCAN_T>>>();
    k_fill<<<(NE + 255) / 256, 256>>>(src, dst);

    k_scale_x<<<(NN * D4 + 255) / 256, 256>>>(h);
    for (int l = 0; l < 3; l++) {
        k_gather<<<(NN * 32 + 255) / 256, 256>>>();
        k_gemm<<<(NN + 31) / 32, 192>>>(Wl[l], Bl[l], l == 2 ? (float*)d_out : nullptr);
    }
}